// round 14
// baseline (speedup 1.0000x reference)
#include <cuda_runtime.h>
#include <cstdint>
#include <cstddef>

#define NB     32
#define NLAT   721
#define NLON   1440
#define NVEC   360          // NLON / 4
#define NWORDS 45           // NLON / 32
#define NUNITS 180          // NLON / 8 (one unit = one mask byte = 8 elements)
#define NTH    96
#define NROWS  (NB * NLAT)  // 23072

// Skewed row: phys(j) = j + 4*(j>>5). Max 1439+4*44 = 1615 -> pad 1620.
#define SXSZ   1620
#define EIDX(j) ((j) + (((j) >> 5) << 2))

// Per-batch (lastrow+1), maintained by rows kernel via atomicMax, consumed
// and RESET by polar kernel each replay. Zero-initialized at module load;
// 0 means "no valid rows".
__device__ int g_lastrow1[NB];

__device__ __forceinline__ bool nan_f(float x) {
    return (__float_as_uint(x) & 0x7FFFFFFFu) > 0x7F800000u;
}

__device__ __forceinline__ unsigned nib_of(float4 r) {
    return (unsigned)(!nan_f(r.x))        | ((unsigned)(!nan_f(r.y)) << 1)
         | ((unsigned)(!nan_f(r.z)) << 2) | ((unsigned)(!nan_f(r.w)) << 3);
}

// ---------------------------------------------------------------------------
// Per-unit (8 contiguous elements) branch-free interpolation.
// ---------------------------------------------------------------------------
__device__ __forceinline__ void do_unit(
    int u, unsigned byte8, float4 rA, float4 rB,
    const float* __restrict__ sx, const int4* __restrict__ wtab,
    float4* __restrict__ dst)
{
    const int w     = u >> 2;
    const int wbase = w << 5;
    const int bpos0 = (u & 3) << 3;                 // 0,8,16,24
    const int4 wt   = wtab[w];                      // one LDS.128 (4-lane bcast)
    const unsigned cur = (unsigned)wt.x;

    // Boundary prev: largest valid strictly below bpos0 (else wt.y).
    const unsigned lomask = (1u << bpos0) - 1u;     // bpos0=0 -> 0
    const unsigned lm = cur & lomask;
    const int prevB = lm ? (wbase + 31 - __clz(lm)) : wt.y;
    // Boundary next: smallest valid strictly above bpos0+7 (else wt.z).
    const unsigned hm = (cur >> (bpos0 + 7)) >> 1;
    const int nextB = hm ? (wbase + bpos0 + 7 + __ffs(hm)) : wt.z;

    // Wrap only for addressing (values); keep unwrapped for arithmetic.
    const int pmi = (prevB < 0)      ? prevB + NLON : prevB;
    const int nmi = (nextB >= NLON)  ? nextB - NLON : nextB;
    const float spB = sx[EIDX(pmi)];
    const float snB = sx[EIDX(nmi)];

    const float fi0 = (float)(u << 3);
    const float fpB = (float)prevB;
    const float fnB = (float)nextB;

    const float RC[8] = {rA.x, rA.y, rA.z, rA.w, rB.x, rB.y, rB.z, rB.w};

    // Ascending prev-index/value chains (1 SEL each per element).
    float FP[8], Q[8];
    {
        float fpc = fpB, qc = spB;
        #pragma unroll
        for (int c = 0; c < 8; c++) {
            const bool v = (byte8 >> c) & 1u;
            fpc = v ? (fi0 + (float)c) : fpc;
            qc  = v ? RC[c]            : qc;
            FP[c] = fpc; Q[c] = qc;
        }
    }
    // Descending next-index/value chains.
    float FN[8], M[8];
    {
        float fnc = fnB, mc = snB;
        #pragma unroll
        for (int c = 7; c >= 0; c--) {
            const bool v = (byte8 >> c) & 1u;
            fnc = v ? (fi0 + (float)c) : fnc;
            mc  = v ? RC[c]            : mc;
            FN[c] = fnc; M[c] = mc;
        }
    }

    float res[8];
    #pragma unroll
    for (int c = 0; c < 8; c++) {
        // NaN element: FP < FI < FN (dt >= 2, exact small ints in float).
        // Valid element: dt==0 -> 0*inf=NaN -> discarded by the select.
        const float fic = fi0 + (float)c;
        const float dp  = fic - FP[c];
        const float dt  = FN[c] - FP[c];
        const float tt  = __fdividef(dp, dt);
        const float iv  = fmaf(tt, M[c] - Q[c], Q[c]);
        res[c] = ((byte8 >> c) & 1u) ? RC[c] : iv;
    }
    dst[2 * u]     = make_float4(res[0], res[1], res[2], res[3]);
    dst[2 * u + 1] = make_float4(res[4], res[5], res[6], res[7]);
}

// ---------------------------------------------------------------------------
// Hot kernel: one 96-thread CTA per row, TWO units per thread (R13 shape).
// Only cross-CTA side effect: one fire-and-forget atomicMax per valid row.
// ---------------------------------------------------------------------------
__global__ void __launch_bounds__(NTH)
fill_rows_kernel(const float4* __restrict__ sst4, float* __restrict__ out)
{
    __shared__ float    sx[SXSZ];       // skewed row
    __shared__ unsigned mask[NWORDS];   // bytes written per-unit, read as words
    __shared__ int4     wtab[NWORDS];   // {mask, prevOutside, nextOutside, 0}

    unsigned char* maskb = (unsigned char*)mask;

    const int row  = blockIdx.x;        // b * NLAT + h
    const int t    = threadIdx.x;
    const int lane = t & 31;
    const int u1   = t;                 // units 0..95
    const int u2   = t + NTH;           // units 96..179 (t < 84)
    const bool has2 = (t < NUNITS - NTH);

    const float4* __restrict__ src = sst4 + (size_t)row * NVEC;
    float4*       __restrict__ dst = (float4*)(out + (size_t)row * NLON);

    // ---- Front-batched loads (4 independent LDG.128) ----
    float4 a0 = src[2 * u1];
    float4 a1 = src[2 * u1 + 1];
    float4 b0 = make_float4(0.f, 0.f, 0.f, 0.f), b1 = b0;
    if (has2) { b0 = src[2 * u2]; b1 = src[2 * u2 + 1]; }

    // ---- Skewed smem store (float4 idx: v + (v>>3)) ----
    float4* sx4 = (float4*)sx;
    {
        const int v0 = 2 * u1, v1 = 2 * u1 + 1;
        sx4[v0 + (v0 >> 3)] = a0;
        sx4[v1 + (v1 >> 3)] = a1;
        if (has2) {
            const int v2 = 2 * u2, v3 = 2 * u2 + 1;
            sx4[v2 + (v2 >> 3)] = b0;
            sx4[v3 + (v3 >> 3)] = b1;
        }
    }

    // ---- Validity byte per unit (mask bytes written directly) ----
    const unsigned byteA = nib_of(a0) | (nib_of(a1) << 4);
    const unsigned byteB = has2 ? (nib_of(b0) | (nib_of(b1) << 4)) : 0u;
    maskb[u1] = (unsigned char)byteA;
    if (has2) maskb[u2] = (unsigned char)byteB;
    __syncthreads();

    // ---- Word-validity bitmap B (redundant per warp: 2 ballots) ----
    const unsigned mwa = (lane < NWORDS)      ? mask[lane]      : 0u;
    const unsigned mwb = (lane + 32 < NWORDS) ? mask[lane + 32] : 0u;
    const unsigned bb1 = __ballot_sync(0xFFFFFFFFu, mwa != 0u);
    const unsigned bb2 = __ballot_sync(0xFFFFFFFFu, mwb != 0u);
    const unsigned long long B = ((unsigned long long)bb2 << 32) | bb1;
    const bool rv = (B != 0ull);

    // Per-batch lastrow+1 (fire-and-forget; no return dependency).
    if (t == 0 && rv) {
        const int b = row / NLAT;
        const int h = row - b * NLAT;
        atomicMax(&g_lastrow1[b], h + 1);
    }

    // ---- Per-word packed table {mask, prev-outside, next-outside} ----
    if (rv && t < NWORDS) {
        const int fw = __ffsll((long long)B) - 1;
        const int firstv = (fw << 5) + __ffs(mask[fw]) - 1;
        const int lw = 63 - __clzll((long long)B);
        const int lastv  = (lw << 5) + 31 - __clz(mask[lw]);

        const unsigned long long lowB = B & ((1ull << t) - 1ull);
        int pv = lastv - NLON;                          // circular wrap
        if (lowB) {
            const int pw = 63 - __clzll((long long)lowB);
            pv = (pw << 5) + 31 - __clz(mask[pw]);
        }

        const unsigned long long highB = B >> (t + 1);
        int nv = firstv + NLON;                         // circular wrap
        if (highB) {
            const int nw = (t + 1) + __ffsll((long long)highB) - 1;
            nv = (nw << 5) + __ffs(mask[nw]) - 1;
        }
        wtab[t] = make_int4((int)mask[t], pv, nv, 0);
    }
    __syncthreads();

    // ---- Branch-free interpolation (8 elements per unit) ----
    if (rv) {
        do_unit(u1, byteA, a0, a1, sx, wtab, dst);
        if (has2) do_unit(u2, byteB, b0, b1, sx, wtab, dst);
    } else {
        dst[2 * u1]     = a0;
        dst[2 * u1 + 1] = a1;
        if (has2) { dst[2 * u2] = b0; dst[2 * u2 + 1] = b1; }
    }
}

// ---------------------------------------------------------------------------
// Polar kernel: one CTA per batch. Reads the precomputed lastrow, resets it
// for the next graph replay, exits immediately in the common case.
// ---------------------------------------------------------------------------
__global__ void __launch_bounds__(128)
fill_polar_kernel(const float* __restrict__ sst, float* __restrict__ out)
{
    const int b   = blockIdx.x;
    const int tid = threadIdx.x;

    __shared__ int s_lr;
    if (tid == 0) {
        s_lr = g_lastrow1[b] - 1;       // -1 = no valid rows in batch
        g_lastrow1[b] = 0;              // reset for next replay
    }
    __syncthreads();

    const int lastrow = s_lr;
    if (lastrow < 0 || lastrow >= NLAT - 1) return;     // common case

    // Fill value row: out[b, lastrow, :] equals the reference's v there.
    const float* __restrict__ fill = out + ((size_t)b * NLAT + lastrow) * NLON;
    for (int h = lastrow + 1; h < NLAT; h++) {
        const float* __restrict__ sr   = sst + ((size_t)b * NLAT + h) * NLON;
        float*       __restrict__ orow = out + ((size_t)b * NLAT + h) * NLON;
        for (int i = tid; i < NLON; i += 128) {
            if (nan_f(sr[i])) orow[i] = fill[i];
        }
    }
}

// ---------------------------------------------------------------------------
extern "C" void kernel_launch(void* const* d_in, const int* in_sizes, int n_in,
                              void* d_out, int out_size)
{
    const float* sst = (const float*)d_in[0];
    float*       out = (float*)d_out;

    fill_rows_kernel<<<NROWS, NTH>>>((const float4*)sst, out);
    fill_polar_kernel<<<NB, 128>>>(sst, out);
}

// round 15
// speedup vs baseline: 1.0170x; 1.0170x over previous
#include <cuda_runtime.h>
#include <cstdint>
#include <cstddef>

#define NB     32
#define NLAT   721
#define NLON   1440
#define NVEC   360          // NLON / 4
#define NWORDS 45           // NLON / 32
#define NUNITS 180          // NLON / 8 (one unit = one mask byte = 8 elements)
#define NTH    96
#define NROWS  (NB * NLAT)  // 23072

// Skewed row: phys(j) = j + 4*(j>>5). Max 1439+4*44 = 1615 -> pad 1620.
#define SXSZ   1620
#define EIDX(j) ((j) + (((j) >> 5) << 2))

// Per-batch (lastrow+1), maintained by rows kernel via atomicMax, consumed
// and RESET by polar kernel each replay. Zero-initialized at module load;
// 0 means "no valid rows".
__device__ int g_lastrow1[NB];

__device__ __forceinline__ bool nan_f(float x) {
    return (__float_as_uint(x) & 0x7FFFFFFFu) > 0x7F800000u;
}

__device__ __forceinline__ unsigned nib_of(float4 r) {
    return (unsigned)(!nan_f(r.x))        | ((unsigned)(!nan_f(r.y)) << 1)
         | ((unsigned)(!nan_f(r.z)) << 2) | ((unsigned)(!nan_f(r.w)) << 3);
}

// ---------------------------------------------------------------------------
// Per-unit (8 contiguous elements) branch-free interpolation.
// ---------------------------------------------------------------------------
__device__ __forceinline__ void do_unit(
    int u, unsigned byte8, float4 rA, float4 rB,
    const float* __restrict__ sx, const int4* __restrict__ wtab,
    float4* __restrict__ dst)
{
    const int w     = u >> 2;
    const int wbase = w << 5;
    const int bpos0 = (u & 3) << 3;                 // 0,8,16,24
    const int4 wt   = wtab[w];                      // one LDS.128 (4-lane bcast)
    const unsigned cur = (unsigned)wt.x;

    // Boundary prev: largest valid strictly below bpos0 (else wt.y).
    const unsigned lomask = (1u << bpos0) - 1u;     // bpos0=0 -> 0
    const unsigned lm = cur & lomask;
    const int prevB = lm ? (wbase + 31 - __clz(lm)) : wt.y;
    // Boundary next: smallest valid strictly above bpos0+7 (else wt.z).
    const unsigned hm = (cur >> (bpos0 + 7)) >> 1;
    const int nextB = hm ? (wbase + bpos0 + 7 + __ffs(hm)) : wt.z;

    // Wrap only for addressing (values); keep unwrapped for arithmetic.
    const int pmi = (prevB < 0)      ? prevB + NLON : prevB;
    const int nmi = (nextB >= NLON)  ? nextB - NLON : nextB;
    const float spB = sx[EIDX(pmi)];
    const float snB = sx[EIDX(nmi)];

    const float fi0 = (float)(u << 3);
    const float fpB = (float)prevB;
    const float fnB = (float)nextB;

    const float RC[8] = {rA.x, rA.y, rA.z, rA.w, rB.x, rB.y, rB.z, rB.w};

    // Ascending prev-index/value chains (1 SEL each per element).
    float FP[8], Q[8];
    {
        float fpc = fpB, qc = spB;
        #pragma unroll
        for (int c = 0; c < 8; c++) {
            const bool v = (byte8 >> c) & 1u;
            fpc = v ? (fi0 + (float)c) : fpc;
            qc  = v ? RC[c]            : qc;
            FP[c] = fpc; Q[c] = qc;
        }
    }
    // Descending next-index/value chains.
    float FN[8], M[8];
    {
        float fnc = fnB, mc = snB;
        #pragma unroll
        for (int c = 7; c >= 0; c--) {
            const bool v = (byte8 >> c) & 1u;
            fnc = v ? (fi0 + (float)c) : fnc;
            mc  = v ? RC[c]            : mc;
            FN[c] = fnc; M[c] = mc;
        }
    }

    float res[8];
    #pragma unroll
    for (int c = 0; c < 8; c++) {
        // NaN element: FP < FI < FN (dt >= 2, exact small ints in float).
        // Valid element: dt==0 -> 0*inf=NaN -> discarded by the select.
        const float fic = fi0 + (float)c;
        const float dp  = fic - FP[c];
        const float dt  = FN[c] - FP[c];
        const float tt  = __fdividef(dp, dt);
        const float iv  = fmaf(tt, M[c] - Q[c], Q[c]);
        res[c] = ((byte8 >> c) & 1u) ? RC[c] : iv;
    }
    dst[2 * u]     = make_float4(res[0], res[1], res[2], res[3]);
    dst[2 * u + 1] = make_float4(res[4], res[5], res[6], res[7]);
}

// ---------------------------------------------------------------------------
// Hot kernel: one 96-thread CTA per row, TWO units per thread (R13 shape).
// Signals PDL dependents after all global writes are issued.
// ---------------------------------------------------------------------------
__global__ void __launch_bounds__(NTH)
fill_rows_kernel(const float4* __restrict__ sst4, float* __restrict__ out)
{
    __shared__ float    sx[SXSZ];       // skewed row
    __shared__ unsigned mask[NWORDS];   // bytes written per-unit, read as words
    __shared__ int4     wtab[NWORDS];   // {mask, prevOutside, nextOutside, 0}

    unsigned char* maskb = (unsigned char*)mask;

    const int row  = blockIdx.x;        // b * NLAT + h
    const int t    = threadIdx.x;
    const int lane = t & 31;
    const int u1   = t;                 // units 0..95
    const int u2   = t + NTH;           // units 96..179 (t < 84)
    const bool has2 = (t < NUNITS - NTH);

    const float4* __restrict__ src = sst4 + (size_t)row * NVEC;
    float4*       __restrict__ dst = (float4*)(out + (size_t)row * NLON);

    // ---- Front-batched loads (4 independent LDG.128) ----
    float4 a0 = src[2 * u1];
    float4 a1 = src[2 * u1 + 1];
    float4 b0 = make_float4(0.f, 0.f, 0.f, 0.f), b1 = b0;
    if (has2) { b0 = src[2 * u2]; b1 = src[2 * u2 + 1]; }

    // ---- Skewed smem store (float4 idx: v + (v>>3)) ----
    float4* sx4 = (float4*)sx;
    {
        const int v0 = 2 * u1, v1 = 2 * u1 + 1;
        sx4[v0 + (v0 >> 3)] = a0;
        sx4[v1 + (v1 >> 3)] = a1;
        if (has2) {
            const int v2 = 2 * u2, v3 = 2 * u2 + 1;
            sx4[v2 + (v2 >> 3)] = b0;
            sx4[v3 + (v3 >> 3)] = b1;
        }
    }

    // ---- Validity byte per unit (mask bytes written directly) ----
    const unsigned byteA = nib_of(a0) | (nib_of(a1) << 4);
    const unsigned byteB = has2 ? (nib_of(b0) | (nib_of(b1) << 4)) : 0u;
    maskb[u1] = (unsigned char)byteA;
    if (has2) maskb[u2] = (unsigned char)byteB;
    __syncthreads();

    // ---- Word-validity bitmap B (redundant per warp: 2 ballots) ----
    const unsigned mwa = (lane < NWORDS)      ? mask[lane]      : 0u;
    const unsigned mwb = (lane + 32 < NWORDS) ? mask[lane + 32] : 0u;
    const unsigned bb1 = __ballot_sync(0xFFFFFFFFu, mwa != 0u);
    const unsigned bb2 = __ballot_sync(0xFFFFFFFFu, mwb != 0u);
    const unsigned long long B = ((unsigned long long)bb2 << 32) | bb1;
    const bool rv = (B != 0ull);

    // Per-batch lastrow+1 (fire-and-forget; no return dependency).
    if (t == 0 && rv) {
        const int b = row / NLAT;
        const int h = row - b * NLAT;
        atomicMax(&g_lastrow1[b], h + 1);
    }

    // ---- Per-word packed table {mask, prev-outside, next-outside} ----
    if (rv && t < NWORDS) {
        const int fw = __ffsll((long long)B) - 1;
        const int firstv = (fw << 5) + __ffs(mask[fw]) - 1;
        const int lw = 63 - __clzll((long long)B);
        const int lastv  = (lw << 5) + 31 - __clz(mask[lw]);

        const unsigned long long lowB = B & ((1ull << t) - 1ull);
        int pv = lastv - NLON;                          // circular wrap
        if (lowB) {
            const int pw = 63 - __clzll((long long)lowB);
            pv = (pw << 5) + 31 - __clz(mask[pw]);
        }

        const unsigned long long highB = B >> (t + 1);
        int nv = firstv + NLON;                         // circular wrap
        if (highB) {
            const int nw = (t + 1) + __ffsll((long long)highB) - 1;
            nv = (nw << 5) + __ffs(mask[nw]) - 1;
        }
        wtab[t] = make_int4((int)mask[t], pv, nv, 0);
    }
    __syncthreads();

    // ---- Branch-free interpolation (8 elements per unit) ----
    if (rv) {
        do_unit(u1, byteA, a0, a1, sx, wtab, dst);
        if (has2) do_unit(u2, byteB, b0, b1, sx, wtab, dst);
    } else {
        dst[2 * u1]     = a0;
        dst[2 * u1 + 1] = a1;
        if (has2) { dst[2 * u2] = b0; dst[2 * u2 + 1] = b1; }
    }

    // PDL: allow dependent (polar) grid to launch; all our global writes
    // are issued above, so they are visible after its griddepcontrol.wait.
    asm volatile("griddepcontrol.launch_dependents;" ::: "memory");
}

// ---------------------------------------------------------------------------
// Polar kernel (PDL dependent): waits for rows' writes, reads precomputed
// lastrow, resets it, exits immediately in the common case.
// ---------------------------------------------------------------------------
__global__ void __launch_bounds__(128)
fill_polar_kernel(const float* __restrict__ sst, float* __restrict__ out)
{
    asm volatile("griddepcontrol.wait;" ::: "memory");

    const int b   = blockIdx.x;
    const int tid = threadIdx.x;

    __shared__ int s_lr;
    if (tid == 0) {
        s_lr = g_lastrow1[b] - 1;       // -1 = no valid rows in batch
        g_lastrow1[b] = 0;              // reset for next replay
    }
    __syncthreads();

    const int lastrow = s_lr;
    if (lastrow < 0 || lastrow >= NLAT - 1) return;     // common case

    // Fill value row: out[b, lastrow, :] equals the reference's v there.
    const float* __restrict__ fill = out + ((size_t)b * NLAT + lastrow) * NLON;
    for (int h = lastrow + 1; h < NLAT; h++) {
        const float* __restrict__ sr   = sst + ((size_t)b * NLAT + h) * NLON;
        float*       __restrict__ orow = out + ((size_t)b * NLAT + h) * NLON;
        for (int i = tid; i < NLON; i += 128) {
            if (nan_f(sr[i])) orow[i] = fill[i];
        }
    }
}

// ---------------------------------------------------------------------------
extern "C" void kernel_launch(void* const* d_in, const int* in_sizes, int n_in,
                              void* d_out, int out_size)
{
    const float* sst = (const float*)d_in[0];
    float*       out = (float*)d_out;

    fill_rows_kernel<<<NROWS, NTH>>>((const float4*)sst, out);

    // Polar launched as a PDL dependent: its CTAs dispatch while rows' tail
    // wave drains, eliminating the inter-kernel gap.
    cudaLaunchConfig_t cfg = {};
    cfg.gridDim  = dim3(NB);
    cfg.blockDim = dim3(128);
    cudaLaunchAttribute attrs[1];
    attrs[0].id = cudaLaunchAttributeProgrammaticStreamSerialization;
    attrs[0].val.programmaticStreamSerializationAllowed = 1;
    cfg.attrs    = attrs;
    cfg.numAttrs = 1;
    cudaLaunchKernelEx(&cfg, fill_polar_kernel, sst, out);
}

// round 16
// speedup vs baseline: 1.0304x; 1.0131x over previous
#include <cuda_runtime.h>
#include <cstdint>
#include <cstddef>

#define NB     32
#define NLAT   721
#define NLON   1440
#define NVEC   360          // NLON / 4
#define NWORDS 45           // NLON / 32
#define NUNITS 180          // NLON / 8 (one unit = one mask byte = 8 elements)
#define NTH    96
#define NROWS  (NB * NLAT)  // 23072

// Skewed row: phys(j) = j + 4*(j>>5). Max 1439+4*44 = 1615 -> pad 1620.
#define SXSZ   1620
#define EIDX(j) ((j) + (((j) >> 5) << 2))

// Per-batch (lastrow+1), maintained by rows kernel via atomicMax, consumed
// and RESET by polar kernel each replay. Zero-initialized at module load;
// 0 means "no valid rows".
__device__ int g_lastrow1[NB];

__device__ __forceinline__ bool nan_f(float x) {
    return (__float_as_uint(x) & 0x7FFFFFFFu) > 0x7F800000u;
}

__device__ __forceinline__ unsigned nib_of(float4 r) {
    return (unsigned)(!nan_f(r.x))        | ((unsigned)(!nan_f(r.y)) << 1)
         | ((unsigned)(!nan_f(r.z)) << 2) | ((unsigned)(!nan_f(r.w)) << 3);
}

// ---------------------------------------------------------------------------
// Per-unit (8 contiguous elements) branch-free interpolation.
// Streaming stores (evict-first): no reuse of out.
// ---------------------------------------------------------------------------
__device__ __forceinline__ void do_unit(
    int u, unsigned byte8, float4 rA, float4 rB,
    const float* __restrict__ sx, const int4* __restrict__ wtab,
    float4* __restrict__ dst)
{
    const int w     = u >> 2;
    const int wbase = w << 5;
    const int bpos0 = (u & 3) << 3;                 // 0,8,16,24
    const int4 wt   = wtab[w];                      // one LDS.128 (4-lane bcast)
    const unsigned cur = (unsigned)wt.x;

    // Boundary prev: largest valid strictly below bpos0 (else wt.y).
    const unsigned lomask = (1u << bpos0) - 1u;     // bpos0=0 -> 0
    const unsigned lm = cur & lomask;
    const int prevB = lm ? (wbase + 31 - __clz(lm)) : wt.y;
    // Boundary next: smallest valid strictly above bpos0+7 (else wt.z).
    const unsigned hm = (cur >> (bpos0 + 7)) >> 1;
    const int nextB = hm ? (wbase + bpos0 + 7 + __ffs(hm)) : wt.z;

    // Wrap only for addressing (values); keep unwrapped for arithmetic.
    const int pmi = (prevB < 0)      ? prevB + NLON : prevB;
    const int nmi = (nextB >= NLON)  ? nextB - NLON : nextB;
    const float spB = sx[EIDX(pmi)];
    const float snB = sx[EIDX(nmi)];

    const float fi0 = (float)(u << 3);
    const float fpB = (float)prevB;
    const float fnB = (float)nextB;

    const float RC[8] = {rA.x, rA.y, rA.z, rA.w, rB.x, rB.y, rB.z, rB.w};

    // Ascending prev-index/value chains (1 SEL each per element).
    float FP[8], Q[8];
    {
        float fpc = fpB, qc = spB;
        #pragma unroll
        for (int c = 0; c < 8; c++) {
            const bool v = (byte8 >> c) & 1u;
            fpc = v ? (fi0 + (float)c) : fpc;
            qc  = v ? RC[c]            : qc;
            FP[c] = fpc; Q[c] = qc;
        }
    }
    // Descending next-index/value chains.
    float FN[8], M[8];
    {
        float fnc = fnB, mc = snB;
        #pragma unroll
        for (int c = 7; c >= 0; c--) {
            const bool v = (byte8 >> c) & 1u;
            fnc = v ? (fi0 + (float)c) : fnc;
            mc  = v ? RC[c]            : mc;
            FN[c] = fnc; M[c] = mc;
        }
    }

    float res[8];
    #pragma unroll
    for (int c = 0; c < 8; c++) {
        // NaN element: FP < FI < FN (dt >= 2, exact small ints in float).
        // Valid element: dt==0 -> 0*inf=NaN -> discarded by the select.
        const float fic = fi0 + (float)c;
        const float dp  = fic - FP[c];
        const float dt  = FN[c] - FP[c];
        const float tt  = __fdividef(dp, dt);
        const float iv  = fmaf(tt, M[c] - Q[c], Q[c]);
        res[c] = ((byte8 >> c) & 1u) ? RC[c] : iv;
    }
    __stcs(&dst[2 * u],     make_float4(res[0], res[1], res[2], res[3]));
    __stcs(&dst[2 * u + 1], make_float4(res[4], res[5], res[6], res[7]));
}

// ---------------------------------------------------------------------------
// Hot kernel: one 96-thread CTA per row, TWO units per thread.
// Streaming loads/stores; signals PDL dependents after all global writes.
// ---------------------------------------------------------------------------
__global__ void __launch_bounds__(NTH)
fill_rows_kernel(const float4* __restrict__ sst4, float* __restrict__ out)
{
    __shared__ float    sx[SXSZ];       // skewed row
    __shared__ unsigned mask[NWORDS];   // bytes written per-unit, read as words
    __shared__ int4     wtab[NWORDS];   // {mask, prevOutside, nextOutside, 0}

    unsigned char* maskb = (unsigned char*)mask;

    const int row  = blockIdx.x;        // b * NLAT + h
    const int t    = threadIdx.x;
    const int lane = t & 31;
    const int u1   = t;                 // units 0..95
    const int u2   = t + NTH;           // units 96..179 (t < 84)
    const bool has2 = (t < NUNITS - NTH);

    const float4* __restrict__ src = sst4 + (size_t)row * NVEC;
    float4*       __restrict__ dst = (float4*)(out + (size_t)row * NLON);

    // ---- Front-batched streaming loads (4 independent LDG.128) ----
    float4 a0 = __ldcs(&src[2 * u1]);
    float4 a1 = __ldcs(&src[2 * u1 + 1]);
    float4 b0 = make_float4(0.f, 0.f, 0.f, 0.f), b1 = b0;
    if (has2) { b0 = __ldcs(&src[2 * u2]); b1 = __ldcs(&src[2 * u2 + 1]); }

    // ---- Skewed smem store (float4 idx: v + (v>>3)) ----
    float4* sx4 = (float4*)sx;
    {
        const int v0 = 2 * u1, v1 = 2 * u1 + 1;
        sx4[v0 + (v0 >> 3)] = a0;
        sx4[v1 + (v1 >> 3)] = a1;
        if (has2) {
            const int v2 = 2 * u2, v3 = 2 * u2 + 1;
            sx4[v2 + (v2 >> 3)] = b0;
            sx4[v3 + (v3 >> 3)] = b1;
        }
    }

    // ---- Validity byte per unit (mask bytes written directly) ----
    const unsigned byteA = nib_of(a0) | (nib_of(a1) << 4);
    const unsigned byteB = has2 ? (nib_of(b0) | (nib_of(b1) << 4)) : 0u;
    maskb[u1] = (unsigned char)byteA;
    if (has2) maskb[u2] = (unsigned char)byteB;
    __syncthreads();

    // ---- Word-validity bitmap B (redundant per warp: 2 ballots) ----
    const unsigned mwa = (lane < NWORDS)      ? mask[lane]      : 0u;
    const unsigned mwb = (lane + 32 < NWORDS) ? mask[lane + 32] : 0u;
    const unsigned bb1 = __ballot_sync(0xFFFFFFFFu, mwa != 0u);
    const unsigned bb2 = __ballot_sync(0xFFFFFFFFu, mwb != 0u);
    const unsigned long long B = ((unsigned long long)bb2 << 32) | bb1;
    const bool rv = (B != 0ull);

    // Per-batch lastrow+1 (fire-and-forget; no return dependency).
    if (t == 0 && rv) {
        const int b = row / NLAT;
        const int h = row - b * NLAT;
        atomicMax(&g_lastrow1[b], h + 1);
    }

    // ---- Per-word packed table {mask, prev-outside, next-outside} ----
    if (rv && t < NWORDS) {
        const int fw = __ffsll((long long)B) - 1;
        const int firstv = (fw << 5) + __ffs(mask[fw]) - 1;
        const int lw = 63 - __clzll((long long)B);
        const int lastv  = (lw << 5) + 31 - __clz(mask[lw]);

        const unsigned long long lowB = B & ((1ull << t) - 1ull);
        int pv = lastv - NLON;                          // circular wrap
        if (lowB) {
            const int pw = 63 - __clzll((long long)lowB);
            pv = (pw << 5) + 31 - __clz(mask[pw]);
        }

        const unsigned long long highB = B >> (t + 1);
        int nv = firstv + NLON;                         // circular wrap
        if (highB) {
            const int nw = (t + 1) + __ffsll((long long)highB) - 1;
            nv = (nw << 5) + __ffs(mask[nw]) - 1;
        }
        wtab[t] = make_int4((int)mask[t], pv, nv, 0);
    }
    __syncthreads();

    // ---- Branch-free interpolation (8 elements per unit) ----
    if (rv) {
        do_unit(u1, byteA, a0, a1, sx, wtab, dst);
        if (has2) do_unit(u2, byteB, b0, b1, sx, wtab, dst);
    } else {
        __stcs(&dst[2 * u1],     a0);
        __stcs(&dst[2 * u1 + 1], a1);
        if (has2) { __stcs(&dst[2 * u2], b0); __stcs(&dst[2 * u2 + 1], b1); }
    }

    // PDL: allow dependent (polar) grid to launch; all our global writes
    // are issued above, so they are visible after its griddepcontrol.wait.
    asm volatile("griddepcontrol.launch_dependents;" ::: "memory");
}

// ---------------------------------------------------------------------------
// Polar kernel (PDL dependent): ONE CTA, 32 threads, one batch per lane.
// Warp-ballot fast exit; warp-cooperative fill in the (never-hit) rare path.
// ---------------------------------------------------------------------------
__global__ void __launch_bounds__(32)
fill_polar_kernel(const float* __restrict__ sst, float* __restrict__ out)
{
    asm volatile("griddepcontrol.wait;" ::: "memory");

    const int lane = threadIdx.x;       // one batch per lane (NB == 32)
    const int lr = g_lastrow1[lane] - 1;            // -1 = no valid rows
    g_lastrow1[lane] = 0;                           // reset for next replay

    const bool need = (lr >= 0) && (lr < NLAT - 1);
    const unsigned bal = __ballot_sync(0xFFFFFFFFu, need);
    if (bal == 0u) return;                          // common case

    // Rare path: whole warp fills each needing batch cooperatively.
    unsigned rem = bal;
    while (rem) {
        const int b = __ffs(rem) - 1;
        rem &= rem - 1u;
        const int blr = __shfl_sync(0xFFFFFFFFu, lr, b);
        const float* __restrict__ fill = out + ((size_t)b * NLAT + blr) * NLON;
        for (int h = blr + 1; h < NLAT; h++) {
            const float* __restrict__ sr   = sst + ((size_t)b * NLAT + h) * NLON;
            float*       __restrict__ orow = out + ((size_t)b * NLAT + h) * NLON;
            for (int i = lane; i < NLON; i += 32) {
                if (nan_f(sr[i])) orow[i] = fill[i];
            }
        }
    }
}

// ---------------------------------------------------------------------------
extern "C" void kernel_launch(void* const* d_in, const int* in_sizes, int n_in,
                              void* d_out, int out_size)
{
    const float* sst = (const float*)d_in[0];
    float*       out = (float*)d_out;

    fill_rows_kernel<<<NROWS, NTH>>>((const float4*)sst, out);

    // Polar launched as a PDL dependent: dispatches while rows' tail drains.
    cudaLaunchConfig_t cfg = {};
    cfg.gridDim  = dim3(1);
    cfg.blockDim = dim3(32);
    cudaLaunchAttribute attrs[1];
    attrs[0].id = cudaLaunchAttributeProgrammaticStreamSerialization;
    attrs[0].val.programmaticStreamSerializationAllowed = 1;
    cfg.attrs    = attrs;
    cfg.numAttrs = 1;
    cudaLaunchKernelEx(&cfg, fill_polar_kernel, sst, out);
}

// round 17
// speedup vs baseline: 1.0498x; 1.0188x over previous
#include <cuda_runtime.h>
#include <cstdint>
#include <cstddef>

#define NB     32
#define NLAT   721
#define NLON   1440
#define NVEC   360          // NLON / 4
#define NWORDS 45           // NLON / 32
#define NUNITS 180          // NLON / 8 (one unit = one mask byte = 8 elements)
#define NTH    96
#define NROWS  (NB * NLAT)  // 23072

// Skewed row: phys(j) = j + 4*(j>>5). Max 1439+4*44 = 1615 -> pad 1620.
#define SXSZ   1620
#define EIDX(j) ((j) + (((j) >> 5) << 2))

typedef unsigned long long u64;

// Packed f32x2 helpers (sm_100+). mov.b64 packs are register-pair aliases
// that ptxas coalesces; fma.rn.f32x2 is the only route to FFMA2.
#define PACK2(out, lo, hi) \
    asm("mov.b64 %0, {%1, %2};" : "=l"(out) \
        : "r"(__float_as_uint(lo)), "r"(__float_as_uint(hi)))
#define UNPACK2(lo, hi, in) do { \
    unsigned _ulo, _uhi; \
    asm("mov.b64 {%0, %1}, %2;" : "=r"(_ulo), "=r"(_uhi) : "l"(in)); \
    lo = __uint_as_float(_ulo); hi = __uint_as_float(_uhi); } while (0)
#define FMA2(out, a, b, c) \
    asm("fma.rn.f32x2 %0, %1, %2, %3;" : "=l"(out) : "l"(a), "l"(b), "l"(c))

// Per-batch (lastrow+1), maintained by rows kernel via atomicMax, consumed
// and RESET by polar kernel each replay. Zero-initialized; 0 = none valid.
__device__ int g_lastrow1[NB];

__device__ __forceinline__ bool nan_f(float x) {
    return (__float_as_uint(x) & 0x7FFFFFFFu) > 0x7F800000u;
}

__device__ __forceinline__ unsigned nib_of(float4 r) {
    return (unsigned)(!nan_f(r.x))        | ((unsigned)(!nan_f(r.y)) << 1)
         | ((unsigned)(!nan_f(r.z)) << 2) | ((unsigned)(!nan_f(r.w)) << 3);
}

// ---------------------------------------------------------------------------
// Per-unit (8 contiguous elements) branch-free interpolation, packed math.
// ---------------------------------------------------------------------------
__device__ __forceinline__ void do_unit(
    int u, unsigned byte8, float4 rA, float4 rB,
    const float* __restrict__ sx, const int4* __restrict__ wtab,
    float4* __restrict__ dst)
{
    const int w     = u >> 2;
    const int wbase = w << 5;
    const int bpos0 = (u & 3) << 3;                 // 0,8,16,24
    const int4 wt   = wtab[w];                      // one LDS.128 (4-lane bcast)
    const unsigned cur = (unsigned)wt.x;

    // Boundary prev: largest valid strictly below bpos0 (else wt.y).
    const unsigned lomask = (1u << bpos0) - 1u;     // bpos0=0 -> 0
    const unsigned lm = cur & lomask;
    const int prevB = lm ? (wbase + 31 - __clz(lm)) : wt.y;
    // Boundary next: smallest valid strictly above bpos0+7 (else wt.z).
    const unsigned hm = (cur >> (bpos0 + 7)) >> 1;
    const int nextB = hm ? (wbase + bpos0 + 7 + __ffs(hm)) : wt.z;

    // Wrap only for addressing (values); keep unwrapped for arithmetic.
    const int pmi = (prevB < 0)      ? prevB + NLON : prevB;
    const int nmi = (nextB >= NLON)  ? nextB - NLON : nextB;
    const float spB = sx[EIDX(pmi)];
    const float snB = sx[EIDX(nmi)];

    const float fi0 = (float)(u << 3);
    const float fpB = (float)prevB;
    const float fnB = (float)nextB;

    const float RC[8] = {rA.x, rA.y, rA.z, rA.w, rB.x, rB.y, rB.z, rB.w};

    // Ascending prev-index/value chains (1 SEL each per element).
    float FP[8], Q[8];
    {
        float fpc = fpB, qc = spB;
        #pragma unroll
        for (int c = 0; c < 8; c++) {
            const bool v = (byte8 >> c) & 1u;
            fpc = v ? (fi0 + (float)c) : fpc;
            qc  = v ? RC[c]            : qc;
            FP[c] = fpc; Q[c] = qc;
        }
    }
    // Descending next-index/value chains.
    float FN[8], M[8];
    {
        float fnc = fnB, mc = snB;
        #pragma unroll
        for (int c = 7; c >= 0; c--) {
            const bool v = (byte8 >> c) & 1u;
            fnc = v ? (fi0 + (float)c) : fnc;
            mc  = v ? RC[c]            : mc;
            FN[c] = fnc; M[c] = mc;
        }
    }

    // Packed res loop: 4 FFMA2 per element-pair instead of 8 scalar FMA ops.
    // fma(x, -1, y) == rn(y - x) exactly ((-1)*x exact, single rounding).
    const u64 NEG1 = 0xBF800000BF800000ull;         // (-1.0f, -1.0f)
    float res[8];
    #pragma unroll
    for (int p = 0; p < 4; p++) {
        const int c0 = 2 * p, c1 = c0 + 1;
        u64 FI2, FP2, FN2, Q2, M2;
        PACK2(FI2, fi0 + (float)c0, fi0 + (float)c1);
        PACK2(FP2, FP[c0], FP[c1]);
        PACK2(FN2, FN[c0], FN[c1]);
        PACK2(Q2,  Q[c0],  Q[c1]);
        PACK2(M2,  M[c0],  M[c1]);

        u64 dp2, dt2, MmQ2;
        FMA2(dp2,  FP2, NEG1, FI2);                 // FI - FP
        FMA2(dt2,  FP2, NEG1, FN2);                 // FN - FP
        FMA2(MmQ2, Q2,  NEG1, M2);                  // M  - Q

        float dp0, dp1, dt0, dt1;
        UNPACK2(dp0, dp1, dp2);
        UNPACK2(dt0, dt1, dt2);
        // NaN element: dt >= 2. Valid element: dt==0 -> NaN, discarded below.
        u64 tt2;
        PACK2(tt2, __fdividef(dp0, dt0), __fdividef(dp1, dt1));

        u64 iv2;
        FMA2(iv2, tt2, MmQ2, Q2);                   // Q + tt*(M-Q)
        float iv0, iv1;
        UNPACK2(iv0, iv1, iv2);

        res[c0] = ((byte8 >> c0) & 1u) ? RC[c0] : iv0;
        res[c1] = ((byte8 >> c1) & 1u) ? RC[c1] : iv1;
    }
    __stcs(&dst[2 * u],     make_float4(res[0], res[1], res[2], res[3]));
    __stcs(&dst[2 * u + 1], make_float4(res[4], res[5], res[6], res[7]));
}

// ---------------------------------------------------------------------------
// Hot kernel: one 96-thread CTA per row, TWO units per thread.
// Streaming loads/stores; signals PDL dependents after all global writes.
// ---------------------------------------------------------------------------
__global__ void __launch_bounds__(NTH)
fill_rows_kernel(const float4* __restrict__ sst4, float* __restrict__ out)
{
    __shared__ float    sx[SXSZ];       // skewed row
    __shared__ unsigned mask[NWORDS];   // bytes written per-unit, read as words
    __shared__ int4     wtab[NWORDS];   // {mask, prevOutside, nextOutside, 0}

    unsigned char* maskb = (unsigned char*)mask;

    const int row  = blockIdx.x;        // b * NLAT + h
    const int t    = threadIdx.x;
    const int lane = t & 31;
    const int u1   = t;                 // units 0..95
    const int u2   = t + NTH;           // units 96..179 (t < 84)
    const bool has2 = (t < NUNITS - NTH);

    const float4* __restrict__ src = sst4 + (size_t)row * NVEC;
    float4*       __restrict__ dst = (float4*)(out + (size_t)row * NLON);

    // ---- Front-batched streaming loads (4 independent LDG.128) ----
    float4 a0 = __ldcs(&src[2 * u1]);
    float4 a1 = __ldcs(&src[2 * u1 + 1]);
    float4 b0 = make_float4(0.f, 0.f, 0.f, 0.f), b1 = b0;
    if (has2) { b0 = __ldcs(&src[2 * u2]); b1 = __ldcs(&src[2 * u2 + 1]); }

    // ---- Skewed smem store (float4 idx: v + (v>>3)) ----
    float4* sx4 = (float4*)sx;
    {
        const int v0 = 2 * u1, v1 = 2 * u1 + 1;
        sx4[v0 + (v0 >> 3)] = a0;
        sx4[v1 + (v1 >> 3)] = a1;
        if (has2) {
            const int v2 = 2 * u2, v3 = 2 * u2 + 1;
            sx4[v2 + (v2 >> 3)] = b0;
            sx4[v3 + (v3 >> 3)] = b1;
        }
    }

    // ---- Validity byte per unit (mask bytes written directly) ----
    const unsigned byteA = nib_of(a0) | (nib_of(a1) << 4);
    const unsigned byteB = has2 ? (nib_of(b0) | (nib_of(b1) << 4)) : 0u;
    maskb[u1] = (unsigned char)byteA;
    if (has2) maskb[u2] = (unsigned char)byteB;
    __syncthreads();

    // ---- Word-validity bitmap B (redundant per warp: 2 ballots) ----
    const unsigned mwa = (lane < NWORDS)      ? mask[lane]      : 0u;
    const unsigned mwb = (lane + 32 < NWORDS) ? mask[lane + 32] : 0u;
    const unsigned bb1 = __ballot_sync(0xFFFFFFFFu, mwa != 0u);
    const unsigned bb2 = __ballot_sync(0xFFFFFFFFu, mwb != 0u);
    const unsigned long long B = ((unsigned long long)bb2 << 32) | bb1;
    const bool rv = (B != 0ull);

    // Per-batch lastrow+1 (fire-and-forget; no return dependency).
    if (t == 0 && rv) {
        const int b = row / NLAT;
        const int h = row - b * NLAT;
        atomicMax(&g_lastrow1[b], h + 1);
    }

    // ---- Per-word packed table {mask, prev-outside, next-outside} ----
    if (rv && t < NWORDS) {
        const int fw = __ffsll((long long)B) - 1;
        const int firstv = (fw << 5) + __ffs(mask[fw]) - 1;
        const int lw = 63 - __clzll((long long)B);
        const int lastv  = (lw << 5) + 31 - __clz(mask[lw]);

        const unsigned long long lowB = B & ((1ull << t) - 1ull);
        int pv = lastv - NLON;                          // circular wrap
        if (lowB) {
            const int pw = 63 - __clzll((long long)lowB);
            pv = (pw << 5) + 31 - __clz(mask[pw]);
        }

        const unsigned long long highB = B >> (t + 1);
        int nv = firstv + NLON;                         // circular wrap
        if (highB) {
            const int nw = (t + 1) + __ffsll((long long)highB) - 1;
            nv = (nw << 5) + __ffs(mask[nw]) - 1;
        }
        wtab[t] = make_int4((int)mask[t], pv, nv, 0);
    }
    __syncthreads();

    // ---- Branch-free interpolation (8 elements per unit) ----
    if (rv) {
        do_unit(u1, byteA, a0, a1, sx, wtab, dst);
        if (has2) do_unit(u2, byteB, b0, b1, sx, wtab, dst);
    } else {
        __stcs(&dst[2 * u1],     a0);
        __stcs(&dst[2 * u1 + 1], a1);
        if (has2) { __stcs(&dst[2 * u2], b0); __stcs(&dst[2 * u2 + 1], b1); }
    }

    // PDL: allow dependent (polar) grid to launch; all our global writes
    // are issued above, so they are visible after its griddepcontrol.wait.
    asm volatile("griddepcontrol.launch_dependents;" ::: "memory");
}

// ---------------------------------------------------------------------------
// Polar kernel (PDL dependent): ONE CTA, 32 threads, one batch per lane.
// Warp-ballot fast exit; warp-cooperative fill in the (never-hit) rare path.
// ---------------------------------------------------------------------------
__global__ void __launch_bounds__(32)
fill_polar_kernel(const float* __restrict__ sst, float* __restrict__ out)
{
    asm volatile("griddepcontrol.wait;" ::: "memory");

    const int lane = threadIdx.x;       // one batch per lane (NB == 32)
    const int lr = g_lastrow1[lane] - 1;            // -1 = no valid rows
    g_lastrow1[lane] = 0;                           // reset for next replay

    const bool need = (lr >= 0) && (lr < NLAT - 1);
    const unsigned bal = __ballot_sync(0xFFFFFFFFu, need);
    if (bal == 0u) return;                          // common case

    // Rare path: whole warp fills each needing batch cooperatively.
    unsigned rem = bal;
    while (rem) {
        const int b = __ffs(rem) - 1;
        rem &= rem - 1u;
        const int blr = __shfl_sync(0xFFFFFFFFu, lr, b);
        const float* __restrict__ fill = out + ((size_t)b * NLAT + blr) * NLON;
        for (int h = blr + 1; h < NLAT; h++) {
            const float* __restrict__ sr   = sst + ((size_t)b * NLAT + h) * NLON;
            float*       __restrict__ orow = out + ((size_t)b * NLAT + h) * NLON;
            for (int i = lane; i < NLON; i += 32) {
                if (nan_f(sr[i])) orow[i] = fill[i];
            }
        }
    }
}

// ---------------------------------------------------------------------------
extern "C" void kernel_launch(void* const* d_in, const int* in_sizes, int n_in,
                              void* d_out, int out_size)
{
    const float* sst = (const float*)d_in[0];
    float*       out = (float*)d_out;

    fill_rows_kernel<<<NROWS, NTH>>>((const float4*)sst, out);

    // Polar launched as a PDL dependent: dispatches while rows' tail drains.
    cudaLaunchConfig_t cfg = {};
    cfg.gridDim  = dim3(1);
    cfg.blockDim = dim3(32);
    cudaLaunchAttribute attrs[1];
    attrs[0].id = cudaLaunchAttributeProgrammaticStreamSerialization;
    attrs[0].val.programmaticStreamSerializationAllowed = 1;
    cfg.attrs    = attrs;
    cfg.numAttrs = 1;
    cudaLaunchKernelEx(&cfg, fill_polar_kernel, sst, out);
}